// round 2
// baseline (speedup 1.0000x reference)
#include <cuda_runtime.h>
#include <cstdint>

#define NCLS 80
#define CAP  512          // per-class candidate cap (mean 315, sd ~18 -> 11 sigma safe)
#define SLOTS (CAP / 32)  // 16 register slots per lane in warp-greedy
#define NTOT 25200        // (6400+1600+400)*3
#define TPA  8            // threads per anchor in decode
#define CPA  (NCLS / TPA) // 10 classes per thread

// Scratch: per-class candidate lists (key = (~score_bits)<<32 | anchor_idx)
__device__ int d_count[NCLS];                       // zero-initialized at load
__device__ unsigned long long d_list[NCLS * CAP];

__constant__ float c_anch[9][2] = {
    {10.f,13.f},{16.f,30.f},{33.f,23.f},
    {30.f,61.f},{62.f,45.f},{59.f,119.f},
    {116.f,90.f},{156.f,198.f},{373.f,326.f}
};

__device__ __forceinline__ float sigm(float x) { return 1.0f / (1.0f + expf(-x)); }

// 8 threads cooperate per anchor. Class logits cached in registers (one read),
// max/argmax + exp-sum reduced across the 8-lane segment via shfl.
__global__ void __launch_bounds__(256) decode_kernel(const float* __restrict__ ps,
                                                     const float* __restrict__ pm,
                                                     const float* __restrict__ pl,
                                                     float* __restrict__ out) {
    int t = blockIdx.x * blockDim.x + threadIdx.x;
    int aidx = t >> 3;
    int q    = t & (TPA - 1);
    if (aidx >= NTOT) return;

    const float* p; int HW, lvl, gbase, tl, ws;
    float stridev;
    if (aidx < 19200)      { p = ps; HW = 6400; stridev =  8.f; lvl = 0; gbase = 0;     tl = aidx;         ws = 80; }
    else if (aidx < 24000) { p = pm; HW = 1600; stridev = 16.f; lvl = 1; gbase = 19200; tl = aidx - 19200; ws = 40; }
    else                   { p = pl; HW =  400; stridev = 32.f; lvl = 2; gbase = 24000; tl = aidx - 24000; ws = 20; }

    int a = tl / HW;
    int i = tl - a * HW;

    // ---- class softmax pieces: this thread owns classes [q*CPA, q*CPA+CPA) ----
    const float* pc = p + (size_t)(3 + a * 80) * HW + i;
    float v[CPA];
    #pragma unroll
    for (int j = 0; j < CPA; j++)
        v[j] = pc[(size_t)(q * CPA + j) * HW];

    float m = v[0];
    int am = q * CPA;
    #pragma unroll
    for (int j = 1; j < CPA; j++)
        if (v[j] > m) { m = v[j]; am = q * CPA + j; }

    // reduce (max, argmax) across the 8-lane segment; ties -> lower class index
    #pragma unroll
    for (int d = TPA / 2; d > 0; d >>= 1) {
        float om = __shfl_down_sync(0xFFFFFFFFu, m,  d, TPA);
        int   oa = __shfl_down_sync(0xFFFFFFFFu, am, d, TPA);
        if (om > m || (om == m && oa < am)) { m = om; am = oa; }
    }
    m  = __shfl_sync(0xFFFFFFFFu, m,  0, TPA);
    am = __shfl_sync(0xFFFFFFFFu, am, 0, TPA);

    float s = 0.0f;
    #pragma unroll
    for (int j = 0; j < CPA; j++)
        s += expf(v[j] - m);
    #pragma unroll
    for (int d = TPA / 2; d > 0; d >>= 1)
        s += __shfl_down_sync(0xFFFFFFFFu, s, d, TPA);

    if (q != 0) return;

    // ---- box decode (lane 0 of segment only) ----
    const float* pr = p + (size_t)(243 + a * 4) * HW + i;
    float gx = (float)(i % ws);
    float gy = (float)(i / ws);
    float cx = (sigm(pr[0])          + gx) * stridev;
    float cy = (sigm(pr[(size_t)HW]) + gy) * stridev;
    float bw = expf(pr[(size_t)2 * HW]) * c_anch[lvl * 3 + a][0];
    float bh = expf(pr[(size_t)3 * HW]) * c_anch[lvl * 3 + a][1];

    float x1 = fminf(fmaxf((cx - bw * 0.5f) / 640.0f, 0.0f), 1.0f);
    float y1 = fminf(fmaxf((cy - bh * 0.5f) / 640.0f, 0.0f), 1.0f);
    float x2 = fminf(fmaxf((cx + bw * 0.5f) / 640.0f, 0.0f), 1.0f);
    float y2 = fminf(fmaxf((cy + bh * 0.5f) / 640.0f, 0.0f), 1.0f);

    float obj   = sigm(p[(size_t)a * HW + i]);
    float score = (1.0f / s) * obj;   // mirror JAX: softmax-at-argmax (1/s) then * obj

    int g = gbase + i * 3 + a;
    float* o = out + (size_t)g * 7;
    o[0] = x1; o[1] = y1; o[2] = x2; o[3] = y2;
    o[4] = score;
    o[5] = (float)am;
    o[6] = 0.0f;

    if (score >= 0.001f) {
        unsigned long long key =
            (((unsigned long long)(0xFFFFFFFFu - __float_as_uint(score))) << 32) |
            (unsigned long long)(unsigned)g;
        int pos = atomicAdd(&d_count[am], 1);
        if (pos < CAP) d_list[(size_t)am * CAP + pos] = key;
    }
}

// One block per class. 256 threads bitonic-sort the candidate keys, gather the
// (class-offset) boxes into shared, then WARP 0 alone runs the serial greedy
// loop with register-resident boxes and shfl-exchanged suppression bitmasks
// (no block barriers in the serial loop).
__global__ void __launch_bounds__(256, 1) nms_kernel(float* __restrict__ out) {
    int c   = blockIdx.x;
    int tid = threadIdx.x;

    __shared__ unsigned long long keys[CAP];
    __shared__ float bx1[CAP], by1[CAP], bx2[CAP], by2[CAP], bar_[CAP];

    int n = d_count[c];
    if (n > CAP) n = CAP;

    for (int t = tid; t < CAP; t += 256)
        keys[t] = (t < n) ? d_list[(size_t)c * CAP + t] : 0xFFFFFFFFFFFFFFFFULL;
    __syncthreads();

    // bitonic sort ascending over CAP=512 (each thread owns 2 slots)
    for (int k = 2; k <= CAP; k <<= 1) {
        for (int j = k >> 1; j > 0; j >>= 1) {
            #pragma unroll
            for (int w = 0; w < CAP / 256; w++) {
                int t = tid + w * 256;
                int ixj = t ^ j;
                if (ixj > t) {
                    bool up = ((t & k) == 0);
                    unsigned long long va = keys[t], vb = keys[ixj];
                    if ((va > vb) == up) { keys[t] = vb; keys[ixj] = va; }
                }
            }
            __syncthreads();
        }
    }

    // gather boxes in sorted order, applying the reference's class offset
    // (+2*cls on all 4 coords) so IoU rounding matches the reference exactly.
    float off = 2.0f * (float)c;
    for (int t = tid; t < n; t += 256) {
        int idx = (int)(keys[t] & 0xFFFFFFFFULL);
        const float* o = out + (size_t)idx * 7;
        float a1 = o[0] + off, b1 = o[1] + off, a2 = o[2] + off, b2 = o[3] + off;
        bx1[t] = a1; by1[t] = b1; bx2[t] = a2; by2[t] = b2;
        bar_[t] = (a2 - a1) * (b2 - b1);
    }
    __syncthreads();

    if (tid < 32) {
        int lane = tid;
        // register-resident boxes: slot s holds item j = s*32 + lane
        float rx1[SLOTS], ry1[SLOTS], rx2[SLOTS], ry2[SLOTS], rar[SLOTS];
        #pragma unroll
        for (int s2 = 0; s2 < SLOTS; s2++) {
            int j = s2 * 32 + lane;
            rx1[s2] = bx1[j]; ry1[s2] = by1[j];
            rx2[s2] = bx2[j]; ry2[s2] = by2[j];
            rar[s2] = bar_[j];
        }
        unsigned suppbits = 0;   // bit s = item s*32+lane suppressed

        for (int i = 0; i < n; i++) {
            unsigned sb = __shfl_sync(0xFFFFFFFFu, suppbits, i & 31);
            if ((sb >> (i >> 5)) & 1u) continue;   // uniform across warp

            if (lane == 0)
                out[(size_t)((int)(keys[i] & 0xFFFFFFFFULL)) * 7 + 6] = 1.0f;

            float X1 = bx1[i], Y1 = by1[i], X2 = bx2[i], Y2 = by2[i], A = bar_[i];

            #pragma unroll
            for (int s2 = 0; s2 < SLOTS; s2++) {
                int j = s2 * 32 + lane;
                if (j > i && j < n) {
                    float xx1 = fmaxf(X1, rx1[s2]);
                    float yy1 = fmaxf(Y1, ry1[s2]);
                    float xx2 = fminf(X2, rx2[s2]);
                    float yy2 = fminf(Y2, ry2[s2]);
                    float w = fmaxf(1e-28f, xx2 - xx1);
                    float h = fmaxf(1e-28f, yy2 - yy1);
                    float inter = w * h;
                    float denom = (A + rar[s2]) - inter;
                    // multiply-prefilter; exact division only near/over threshold
                    if (denom > 0.0f && inter > 0.599f * denom) {
                        if (inter / denom > 0.6f) suppbits |= (1u << s2);
                    }
                }
            }
        }
    }

    // reset counter for the next replay (zero-init covers the very first call)
    if (tid == 0) d_count[c] = 0;
}

extern "C" void kernel_launch(void* const* d_in, const int* in_sizes, int n_in,
                              void* d_out, int out_size) {
    const float* ps = (const float*)d_in[0];
    const float* pm = (const float*)d_in[1];
    const float* pl = (const float*)d_in[2];
    float* out = (float*)d_out;

    decode_kernel<<<(NTOT * TPA + 255) / 256, 256>>>(ps, pm, pl, out);
    nms_kernel<<<NCLS, 256>>>(out);
}

// round 3
// speedup vs baseline: 2.6220x; 2.6220x over previous
#include <cuda_runtime.h>
#include <cstdint>

#define NCLS 80
#define CAP  512          // per-class candidate cap (mean 315, sd ~18)
#define NW   (CAP / 32)   // 16 mask words per row
#define NTOT 25200        // (6400+1600+400)*3
#define TPA  8            // threads per anchor in decode
#define CPA  (NCLS / TPA) // 10 classes per thread

// Scratch: per-class candidate lists (key = (~score_bits)<<32 | anchor_idx)
__device__ int d_count[NCLS];                       // zero-initialized at load
__device__ unsigned long long d_list[NCLS * CAP];

__constant__ float c_anch[9][2] = {
    {10.f,13.f},{16.f,30.f},{33.f,23.f},
    {30.f,61.f},{62.f,45.f},{59.f,119.f},
    {116.f,90.f},{156.f,198.f},{373.f,326.f}
};

__device__ __forceinline__ float sigm(float x) { return 1.0f / (1.0f + expf(-x)); }

// 8 threads cooperate per anchor. Class logits cached in registers (one read),
// max/argmax + exp-sum reduced across the 8-lane segment via shfl.
__global__ void __launch_bounds__(256) decode_kernel(const float* __restrict__ ps,
                                                     const float* __restrict__ pm,
                                                     const float* __restrict__ pl,
                                                     float* __restrict__ out) {
    int t = blockIdx.x * blockDim.x + threadIdx.x;
    int aidx = t >> 3;
    int q    = t & (TPA - 1);
    if (aidx >= NTOT) return;

    const float* p; int HW, lvl, gbase, tl, ws;
    float stridev;
    if (aidx < 19200)      { p = ps; HW = 6400; stridev =  8.f; lvl = 0; gbase = 0;     tl = aidx;         ws = 80; }
    else if (aidx < 24000) { p = pm; HW = 1600; stridev = 16.f; lvl = 1; gbase = 19200; tl = aidx - 19200; ws = 40; }
    else                   { p = pl; HW =  400; stridev = 32.f; lvl = 2; gbase = 24000; tl = aidx - 24000; ws = 20; }

    int a = tl / HW;
    int i = tl - a * HW;

    // ---- class softmax pieces: this thread owns classes [q*CPA, q*CPA+CPA) ----
    const float* pc = p + (size_t)(3 + a * 80) * HW + i;
    float v[CPA];
    #pragma unroll
    for (int j = 0; j < CPA; j++)
        v[j] = pc[(size_t)(q * CPA + j) * HW];

    float m = v[0];
    int am = q * CPA;
    #pragma unroll
    for (int j = 1; j < CPA; j++)
        if (v[j] > m) { m = v[j]; am = q * CPA + j; }

    // reduce (max, argmax) across the 8-lane segment; ties -> lower class index
    #pragma unroll
    for (int d = TPA / 2; d > 0; d >>= 1) {
        float om = __shfl_down_sync(0xFFFFFFFFu, m,  d, TPA);
        int   oa = __shfl_down_sync(0xFFFFFFFFu, am, d, TPA);
        if (om > m || (om == m && oa < am)) { m = om; am = oa; }
    }
    m  = __shfl_sync(0xFFFFFFFFu, m,  0, TPA);
    am = __shfl_sync(0xFFFFFFFFu, am, 0, TPA);

    float s = 0.0f;
    #pragma unroll
    for (int j = 0; j < CPA; j++)
        s += expf(v[j] - m);
    #pragma unroll
    for (int d = TPA / 2; d > 0; d >>= 1)
        s += __shfl_down_sync(0xFFFFFFFFu, s, d, TPA);

    if (q != 0) return;

    // ---- box decode (lane 0 of segment only) ----
    const float* pr = p + (size_t)(243 + a * 4) * HW + i;
    float gx = (float)(i % ws);
    float gy = (float)(i / ws);
    float cx = (sigm(pr[0])          + gx) * stridev;
    float cy = (sigm(pr[(size_t)HW]) + gy) * stridev;
    float bw = expf(pr[(size_t)2 * HW]) * c_anch[lvl * 3 + a][0];
    float bh = expf(pr[(size_t)3 * HW]) * c_anch[lvl * 3 + a][1];

    float x1 = fminf(fmaxf((cx - bw * 0.5f) / 640.0f, 0.0f), 1.0f);
    float y1 = fminf(fmaxf((cy - bh * 0.5f) / 640.0f, 0.0f), 1.0f);
    float x2 = fminf(fmaxf((cx + bw * 0.5f) / 640.0f, 0.0f), 1.0f);
    float y2 = fminf(fmaxf((cy + bh * 0.5f) / 640.0f, 0.0f), 1.0f);

    float obj   = sigm(p[(size_t)a * HW + i]);
    float score = (1.0f / s) * obj;   // softmax-at-argmax (1/s) then * obj

    int g = gbase + i * 3 + a;
    float* o = out + (size_t)g * 7;
    o[0] = x1; o[1] = y1; o[2] = x2; o[3] = y2;
    o[4] = score;
    o[5] = (float)am;
    o[6] = 0.0f;

    if (score >= 0.001f) {
        unsigned long long key =
            (((unsigned long long)(0xFFFFFFFFu - __float_as_uint(score))) << 32) |
            (unsigned long long)(unsigned)g;
        int pos = atomicAdd(&d_count[am], 1);
        if (pos < CAP) d_list[(size_t)am * CAP + pos] = key;
    }
}

// One block per class. Bitonic sort -> pairwise suppression bitmask (fully
// parallel) -> cheap serial OR-scan on warp 0 (no IoU in the serial part).
__global__ void __launch_bounds__(256, 1) nms_kernel(float* __restrict__ out) {
    int c   = blockIdx.x;
    int tid = threadIdx.x;

    __shared__ unsigned long long keys[CAP];     //  4 KB
    __shared__ float4  bb[CAP];                  //  8 KB (x1,y1,x2,y2 + class offset)
    __shared__ unsigned mask[CAP * NW];          // 32 KB suppression matrix

    int n = d_count[c];
    if (n > CAP) n = CAP;
    if (tid == 0) d_count[c] = 0;                // reset for next replay

    if (n > 0) {
        for (int t = tid; t < CAP; t += 256)
            keys[t] = (t < n) ? d_list[(size_t)c * CAP + t] : 0xFFFFFFFFFFFFFFFFULL;
        __syncthreads();

        // bitonic sort ascending over CAP=512 (score desc, idx asc)
        for (int k = 2; k <= CAP; k <<= 1) {
            for (int j = k >> 1; j > 0; j >>= 1) {
                #pragma unroll
                for (int w = 0; w < CAP / 256; w++) {
                    int t = tid + w * 256;
                    int ixj = t ^ j;
                    if (ixj > t) {
                        bool up = ((t & k) == 0);
                        unsigned long long va = keys[t], vb = keys[ixj];
                        if ((va > vb) == up) { keys[t] = vb; keys[ixj] = va; }
                    }
                }
                __syncthreads();
            }
        }

        // gather boxes in sorted order with the reference's class offset
        float off = 2.0f * (float)c;
        for (int t = tid; t < n; t += 256) {
            int idx = (int)(keys[t] & 0xFFFFFFFFULL);
            const float* o = out + (size_t)idx * 7;
            bb[t] = make_float4(o[0] + off, o[1] + off, o[2] + off, o[3] + off);
        }
        __syncthreads();

        // pairwise suppression matrix: row i, word w covers j in [w*32, w*32+32)
        int nw = (n + 31) >> 5;
        int items = n * nw;
        for (int it = tid; it < items; it += 256) {
            int i = it / nw;
            int w = it - i * nw;
            int j0 = w << 5;
            unsigned bits = 0;
            if (j0 + 31 > i) {                  // word has at least one j > i
                float4 bi = bb[i];
                float aI = (bi.z - bi.x) * (bi.w - bi.y);
                int jend = min(j0 + 32, n);
                for (int j = max(j0, i + 1); j < jend; j++) {
                    float4 bj = bb[j];
                    float xx1 = fmaxf(bi.x, bj.x);
                    float yy1 = fmaxf(bi.y, bj.y);
                    float xx2 = fminf(bi.z, bj.z);
                    float yy2 = fminf(bi.w, bj.w);
                    float w_ = fmaxf(1e-28f, xx2 - xx1);
                    float h_ = fmaxf(1e-28f, yy2 - yy1);
                    float inter = w_ * h_;
                    float aJ = (bj.z - bj.x) * (bj.w - bj.y);
                    float denom = (aI + aJ) - inter;
                    if (denom > 0.0f && inter > 0.599f * denom) {
                        if (inter / denom > 0.6f) bits |= (1u << (j & 31));
                    }
                }
            }
            mask[i * NW + w] = bits;
        }
        __syncthreads();

        // serial OR-scan on warp 0: lane = mask word index
        if (tid < 32) {
            unsigned removed = 0;               // lane w owns removed-word w
            for (int i = 0; i < n; i++) {
                unsigned g = __shfl_sync(0xFFFFFFFFu, removed, i >> 5);
                if (!((g >> (i & 31)) & 1u)) {  // uniform branch
                    if (tid == 0)
                        out[(size_t)((int)(keys[i] & 0xFFFFFFFFULL)) * 7 + 6] = 1.0f;
                    removed |= mask[i * NW + tid];
                }
            }
        }
    }
}

extern "C" void kernel_launch(void* const* d_in, const int* in_sizes, int n_in,
                              void* d_out, int out_size) {
    const float* ps = (const float*)d_in[0];
    const float* pm = (const float*)d_in[1];
    const float* pl = (const float*)d_in[2];
    float* out = (float*)d_out;

    decode_kernel<<<(NTOT * TPA + 255) / 256, 256>>>(ps, pm, pl, out);
    nms_kernel<<<NCLS, 256>>>(out);
}

// round 4
// speedup vs baseline: 3.1949x; 1.2185x over previous
#include <cuda_runtime.h>
#include <cstdint>

#define NCLS 80
#define CAP  512          // per-class candidate cap (mean 315, max ~375 for seed 0)
#define NW   (CAP / 32)   // 16 mask words per row
#define NTOT 25200        // (6400+1600+400)*3
#define TPA  8            // threads per anchor in decode
#define CPA  (NCLS / TPA) // 10 classes per thread

// Scratch: per-class candidate lists (key = (~score_bits)<<32 | anchor_idx)
__device__ int d_count[NCLS];                       // zero-initialized at load
__device__ unsigned long long d_list[NCLS * CAP];

__constant__ float c_anch[9][2] = {
    {10.f,13.f},{16.f,30.f},{33.f,23.f},
    {30.f,61.f},{62.f,45.f},{59.f,119.f},
    {116.f,90.f},{156.f,198.f},{373.f,326.f}
};

__device__ __forceinline__ float sigm(float x) { return 1.0f / (1.0f + expf(-x)); }

// 8 threads cooperate per anchor. Class logits cached in registers (one read),
// max/argmax + exp-sum reduced across the 8-lane segment via shfl.
__global__ void __launch_bounds__(256) decode_kernel(const float* __restrict__ ps,
                                                     const float* __restrict__ pm,
                                                     const float* __restrict__ pl,
                                                     float* __restrict__ out) {
    int t = blockIdx.x * blockDim.x + threadIdx.x;
    int aidx = t >> 3;
    int q    = t & (TPA - 1);
    if (aidx >= NTOT) return;

    const float* p; int HW, lvl, gbase, tl, ws;
    float stridev;
    if (aidx < 19200)      { p = ps; HW = 6400; stridev =  8.f; lvl = 0; gbase = 0;     tl = aidx;         ws = 80; }
    else if (aidx < 24000) { p = pm; HW = 1600; stridev = 16.f; lvl = 1; gbase = 19200; tl = aidx - 19200; ws = 40; }
    else                   { p = pl; HW =  400; stridev = 32.f; lvl = 2; gbase = 24000; tl = aidx - 24000; ws = 20; }

    int a = tl / HW;
    int i = tl - a * HW;

    // ---- class softmax pieces: this thread owns classes [q*CPA, q*CPA+CPA) ----
    const float* pc = p + (size_t)(3 + a * 80) * HW + i;
    float v[CPA];
    #pragma unroll
    for (int j = 0; j < CPA; j++)
        v[j] = pc[(size_t)(q * CPA + j) * HW];

    float m = v[0];
    int am = q * CPA;
    #pragma unroll
    for (int j = 1; j < CPA; j++)
        if (v[j] > m) { m = v[j]; am = q * CPA + j; }

    // reduce (max, argmax) across the 8-lane segment; ties -> lower class index
    #pragma unroll
    for (int d = TPA / 2; d > 0; d >>= 1) {
        float om = __shfl_down_sync(0xFFFFFFFFu, m,  d, TPA);
        int   oa = __shfl_down_sync(0xFFFFFFFFu, am, d, TPA);
        if (om > m || (om == m && oa < am)) { m = om; am = oa; }
    }
    m  = __shfl_sync(0xFFFFFFFFu, m,  0, TPA);
    am = __shfl_sync(0xFFFFFFFFu, am, 0, TPA);

    float s = 0.0f;
    #pragma unroll
    for (int j = 0; j < CPA; j++)
        s += expf(v[j] - m);
    #pragma unroll
    for (int d = TPA / 2; d > 0; d >>= 1)
        s += __shfl_down_sync(0xFFFFFFFFu, s, d, TPA);

    if (q != 0) return;

    // ---- box decode (lane 0 of segment only) ----
    const float* pr = p + (size_t)(243 + a * 4) * HW + i;
    float gx = (float)(i % ws);
    float gy = (float)(i / ws);
    float cx = (sigm(pr[0])          + gx) * stridev;
    float cy = (sigm(pr[(size_t)HW]) + gy) * stridev;
    float bw = expf(pr[(size_t)2 * HW]) * c_anch[lvl * 3 + a][0];
    float bh = expf(pr[(size_t)3 * HW]) * c_anch[lvl * 3 + a][1];

    float x1 = fminf(fmaxf((cx - bw * 0.5f) / 640.0f, 0.0f), 1.0f);
    float y1 = fminf(fmaxf((cy - bh * 0.5f) / 640.0f, 0.0f), 1.0f);
    float x2 = fminf(fmaxf((cx + bw * 0.5f) / 640.0f, 0.0f), 1.0f);
    float y2 = fminf(fmaxf((cy + bh * 0.5f) / 640.0f, 0.0f), 1.0f);

    float obj   = sigm(p[(size_t)a * HW + i]);
    float score = (1.0f / s) * obj;   // softmax-at-argmax (1/s) then * obj

    int g = gbase + i * 3 + a;
    float* o = out + (size_t)g * 7;
    o[0] = x1; o[1] = y1; o[2] = x2; o[3] = y2;
    o[4] = score;
    o[5] = (float)am;
    o[6] = 0.0f;

    if (score >= 0.001f) {
        unsigned long long key =
            (((unsigned long long)(0xFFFFFFFFu - __float_as_uint(score))) << 32) |
            (unsigned long long)(unsigned)g;
        int pos = atomicAdd(&d_count[am], 1);
        if (pos < CAP) d_list[(size_t)am * CAP + pos] = key;
    }
}

// One block (512 threads) per class. Bitonic sort -> pairwise suppression
// bitmask (fully parallel) -> single-thread register-resident OR-scan
// (no shfl, no divergence machinery, LDS.128 row loads only for kept boxes).
__global__ void __launch_bounds__(512, 1) nms_kernel(float* __restrict__ out) {
    int c   = blockIdx.x;
    int tid = threadIdx.x;

    __shared__ unsigned long long keys[CAP];     //  4 KB
    __shared__ float4  bb[CAP];                  //  8 KB (x1,y1,x2,y2 + class offset)
    __shared__ unsigned mask[CAP * NW];          // 32 KB suppression matrix

    int n = d_count[c];
    if (n > CAP) n = CAP;
    if (tid == 0) d_count[c] = 0;                // reset for next replay

    if (n > 0) {
        if (tid < CAP)
            keys[tid] = (tid < n) ? d_list[(size_t)c * CAP + tid] : 0xFFFFFFFFFFFFFFFFULL;
        __syncthreads();

        // bitonic sort ascending over CAP=512 (score desc, idx asc); 1 elem/thread
        for (int k = 2; k <= CAP; k <<= 1) {
            for (int j = k >> 1; j > 0; j >>= 1) {
                int t = tid;
                int ixj = t ^ j;
                if (ixj > t && t < CAP) {
                    bool up = ((t & k) == 0);
                    unsigned long long va = keys[t], vb = keys[ixj];
                    if ((va > vb) == up) { keys[t] = vb; keys[ixj] = va; }
                }
                __syncthreads();
            }
        }

        // gather boxes in sorted order with the reference's class offset
        float off = 2.0f * (float)c;
        if (tid < n) {
            int idx = (int)(keys[tid] & 0xFFFFFFFFULL);
            const float* o = out + (size_t)idx * 7;
            bb[tid] = make_float4(o[0] + off, o[1] + off, o[2] + off, o[3] + off);
        }
        __syncthreads();

        // pairwise suppression matrix: row i, word w covers j in [w*32, w*32+32).
        // All NW words of every row are written (zeros beyond n) so the scan
        // can OR full rows unconditionally.
        int items = n * NW;
        for (int it = tid; it < items; it += 512) {
            int i = it >> 4;          // it / NW
            int w = it & (NW - 1);    // it % NW
            int j0 = w << 5;
            unsigned bits = 0;
            if (j0 + 31 > i && j0 < n) {
                float4 bi = bb[i];
                float aI = (bi.z - bi.x) * (bi.w - bi.y);
                int jend = min(j0 + 32, n);
                for (int j = max(j0, i + 1); j < jend; j++) {
                    float4 bj = bb[j];
                    float xx1 = fmaxf(bi.x, bj.x);
                    float yy1 = fmaxf(bi.y, bj.y);
                    float xx2 = fminf(bi.z, bj.z);
                    float yy2 = fminf(bi.w, bj.w);
                    float w_ = fmaxf(1e-28f, xx2 - xx1);
                    float h_ = fmaxf(1e-28f, yy2 - yy1);
                    float inter = w_ * h_;
                    float aJ = (bj.z - bj.x) * (bj.w - bj.y);
                    float denom = (aI + aJ) - inter;
                    if (denom > 0.0f && inter > 0.599f * denom) {
                        if (inter / denom > 0.6f) bits |= (1u << (j & 31));
                    }
                }
            }
            mask[i * NW + w] = bits;
        }
        __syncthreads();

        // serial OR-scan: ONE thread, removed words in registers, no shfl.
        if (tid == 0) {
            unsigned rem[NW];
            #pragma unroll
            for (int w = 0; w < NW; w++) rem[w] = 0;

            #pragma unroll
            for (int w = 0; w < NW; w++) {
                if (w * 32 < n) {
                    int bend = min(32, n - w * 32);
                    for (int b = 0; b < bend; b++) {
                        if (!((rem[w] >> b) & 1u)) {
                            int i = w * 32 + b;
                            out[(size_t)((int)(keys[i] & 0xFFFFFFFFULL)) * 7 + 6] = 1.0f;
                            const uint4* row = (const uint4*)&mask[i * NW];
                            uint4 m0 = row[0], m1 = row[1], m2 = row[2], m3 = row[3];
                            rem[0]  |= m0.x; rem[1]  |= m0.y; rem[2]  |= m0.z; rem[3]  |= m0.w;
                            rem[4]  |= m1.x; rem[5]  |= m1.y; rem[6]  |= m1.z; rem[7]  |= m1.w;
                            rem[8]  |= m2.x; rem[9]  |= m2.y; rem[10] |= m2.z; rem[11] |= m2.w;
                            rem[12] |= m3.x; rem[13] |= m3.y; rem[14] |= m3.z; rem[15] |= m3.w;
                        }
                    }
                }
            }
        }
    }
}

extern "C" void kernel_launch(void* const* d_in, const int* in_sizes, int n_in,
                              void* d_out, int out_size) {
    const float* ps = (const float*)d_in[0];
    const float* pm = (const float*)d_in[1];
    const float* pl = (const float*)d_in[2];
    float* out = (float*)d_out;

    decode_kernel<<<(NTOT * TPA + 255) / 256, 256>>>(ps, pm, pl, out);
    nms_kernel<<<NCLS, 512>>>(out);
}

// round 5
// speedup vs baseline: 4.0580x; 1.2701x over previous
#include <cuda_runtime.h>
#include <cstdint>

#define NCLS 80
#define CAP  512          // per-class candidate cap (mean 315, max ~375 for seed 0)
#define NW   (CAP / 32)   // 16 mask words per row
#define NTOT 25200        // (6400+1600+400)*3
#define TPA  8            // threads per anchor in decode
#define CPA  (NCLS / TPA) // 10 classes per thread

// Scratch: per-class candidate lists (key = (~score_bits)<<32 | anchor_idx)
__device__ int d_count[NCLS];                       // zero-initialized at load
__device__ unsigned long long d_list[NCLS * CAP];

__constant__ float c_anch[9][2] = {
    {10.f,13.f},{16.f,30.f},{33.f,23.f},
    {30.f,61.f},{62.f,45.f},{59.f,119.f},
    {116.f,90.f},{156.f,198.f},{373.f,326.f}
};

__device__ __forceinline__ float sigm(float x) { return 1.0f / (1.0f + expf(-x)); }

// 8 threads cooperate per anchor. Class logits cached in registers (one read),
// max/argmax + exp-sum reduced across the 8-lane segment via shfl.
__global__ void __launch_bounds__(256) decode_kernel(const float* __restrict__ ps,
                                                     const float* __restrict__ pm,
                                                     const float* __restrict__ pl,
                                                     float* __restrict__ out) {
    int t = blockIdx.x * blockDim.x + threadIdx.x;
    int aidx = t >> 3;
    int q    = t & (TPA - 1);
    if (aidx >= NTOT) return;

    const float* p; int HW, lvl, gbase, tl, ws;
    float stridev;
    if (aidx < 19200)      { p = ps; HW = 6400; stridev =  8.f; lvl = 0; gbase = 0;     tl = aidx;         ws = 80; }
    else if (aidx < 24000) { p = pm; HW = 1600; stridev = 16.f; lvl = 1; gbase = 19200; tl = aidx - 19200; ws = 40; }
    else                   { p = pl; HW =  400; stridev = 32.f; lvl = 2; gbase = 24000; tl = aidx - 24000; ws = 20; }

    int a = tl / HW;
    int i = tl - a * HW;

    const float* pc = p + (size_t)(3 + a * 80) * HW + i;
    float v[CPA];
    #pragma unroll
    for (int j = 0; j < CPA; j++)
        v[j] = pc[(size_t)(q * CPA + j) * HW];

    float m = v[0];
    int am = q * CPA;
    #pragma unroll
    for (int j = 1; j < CPA; j++)
        if (v[j] > m) { m = v[j]; am = q * CPA + j; }

    #pragma unroll
    for (int d = TPA / 2; d > 0; d >>= 1) {
        float om = __shfl_down_sync(0xFFFFFFFFu, m,  d, TPA);
        int   oa = __shfl_down_sync(0xFFFFFFFFu, am, d, TPA);
        if (om > m || (om == m && oa < am)) { m = om; am = oa; }
    }
    m  = __shfl_sync(0xFFFFFFFFu, m,  0, TPA);
    am = __shfl_sync(0xFFFFFFFFu, am, 0, TPA);

    float s = 0.0f;
    #pragma unroll
    for (int j = 0; j < CPA; j++)
        s += expf(v[j] - m);
    #pragma unroll
    for (int d = TPA / 2; d > 0; d >>= 1)
        s += __shfl_down_sync(0xFFFFFFFFu, s, d, TPA);

    if (q != 0) return;

    const float* pr = p + (size_t)(243 + a * 4) * HW + i;
    float gx = (float)(i % ws);
    float gy = (float)(i / ws);
    float cx = (sigm(pr[0])          + gx) * stridev;
    float cy = (sigm(pr[(size_t)HW]) + gy) * stridev;
    float bw = expf(pr[(size_t)2 * HW]) * c_anch[lvl * 3 + a][0];
    float bh = expf(pr[(size_t)3 * HW]) * c_anch[lvl * 3 + a][1];

    float x1 = fminf(fmaxf((cx - bw * 0.5f) / 640.0f, 0.0f), 1.0f);
    float y1 = fminf(fmaxf((cy - bh * 0.5f) / 640.0f, 0.0f), 1.0f);
    float x2 = fminf(fmaxf((cx + bw * 0.5f) / 640.0f, 0.0f), 1.0f);
    float y2 = fminf(fmaxf((cy + bh * 0.5f) / 640.0f, 0.0f), 1.0f);

    float obj   = sigm(p[(size_t)a * HW + i]);
    float score = (1.0f / s) * obj;

    int g = gbase + i * 3 + a;
    float* o = out + (size_t)g * 7;
    o[0] = x1; o[1] = y1; o[2] = x2; o[3] = y2;
    o[4] = score;
    o[5] = (float)am;
    o[6] = 0.0f;

    if (score >= 0.001f) {
        unsigned long long key =
            (((unsigned long long)(0xFFFFFFFFu - __float_as_uint(score))) << 32) |
            (unsigned long long)(unsigned)g;
        int pos = atomicAdd(&d_count[am], 1);
        if (pos < CAP) d_list[(size_t)am * CAP + pos] = key;
    }
}

// One block (512 threads) per class.
// 1) hybrid register/shfl bitonic sort (keys desc by score)
// 2) row-per-thread suppression-mask build: j uniform across warp -> LDS broadcast
// 3) single-thread OR-scan that only touches rows flagged as suppressing
__global__ void __launch_bounds__(512, 1) nms_kernel(float* __restrict__ out) {
    int c   = blockIdx.x;
    int tid = threadIdx.x;

    __shared__ unsigned long long keys[CAP];     //  4 KB
    __shared__ float4  bb[CAP];                  //  8 KB
    __shared__ unsigned mask[CAP * NW];          // 32 KB suppression matrix
    __shared__ unsigned flagw[NW];               // per-row any-suppression bits
    __shared__ int sn;

    if (tid == 0) {
        int nn = d_count[c];
        sn = (nn > CAP) ? CAP : nn;
        d_count[c] = 0;                          // reset for next replay (ordered: same thread)
    }
    __syncthreads();
    int n = sn;

    // ---- load keys into registers (sentinel pad) ----
    unsigned long long r = (tid < n) ? d_list[(size_t)c * CAP + tid]
                                     : 0xFFFFFFFFFFFFFFFFULL;

    // ---- bitonic sort (ascending key = descending score, idx asc) ----
    // intra-warp phases k=2..32: pure shfl
    #pragma unroll
    for (int k = 2; k <= 32; k <<= 1) {
        bool up = ((tid & k) == 0);
        #pragma unroll
        for (int j = k >> 1; j >= 1; j >>= 1) {
            unsigned long long o = __shfl_xor_sync(0xFFFFFFFFu, r, j);
            bool takeMin = (((tid & j) == 0) == up);
            bool less = (o < r);
            r = takeMin ? (less ? o : r) : (less ? r : o);
        }
    }
    // phases k=64..512: cross-warp steps through shared, tail via shfl
    #pragma unroll
    for (int k = 64; k <= CAP; k <<= 1) {
        bool up = ((tid & k) == 0);
        for (int j = k >> 1; j >= 32; j >>= 1) {
            keys[tid] = r;
            __syncthreads();
            unsigned long long o = keys[tid ^ j];
            bool takeMin = (((tid & j) == 0) == up);
            bool less = (o < r);
            r = takeMin ? (less ? o : r) : (less ? r : o);
            __syncthreads();
        }
        #pragma unroll
        for (int j = 16; j >= 1; j >>= 1) {
            unsigned long long o = __shfl_xor_sync(0xFFFFFFFFu, r, j);
            bool takeMin = (((tid & j) == 0) == up);
            bool less = (o < r);
            r = takeMin ? (less ? o : r) : (less ? r : o);
        }
    }
    keys[tid] = r;
    __syncthreads();

    // ---- gather boxes in sorted order with the reference's class offset ----
    float off = 2.0f * (float)c;
    if (tid < n) {
        int idx = (int)(keys[tid] & 0xFFFFFFFFULL);
        const float* o = out + (size_t)idx * 7;
        bb[tid] = make_float4(o[0] + off, o[1] + off, o[2] + off, o[3] + off);
    }
    __syncthreads();

    // ---- mask build: thread tid owns row i=tid. j uniform across warp. ----
    unsigned any = 0;
    if (tid < n) {
        // zero full row (4x STS.128) so the scan can OR unconditionally
        uint4* rowp = (uint4*)&mask[tid * NW];
        uint4 z = make_uint4(0, 0, 0, 0);
        rowp[0] = z; rowp[1] = z; rowp[2] = z; rowp[3] = z;

        float4 bi = bb[tid];
        float aI = (bi.z - bi.x) * (bi.w - bi.y);
        int wbeg = (tid + 1) >> 5;
        int wend = (n + 31) >> 5;
        for (int w = wbeg; w < wend; w++) {
            int j0   = w << 5;
            int jbeg = max(j0, tid + 1);
            int jend = min(j0 + 32, n);
            unsigned bits = 0;
            for (int j = jbeg; j < jend; j++) {
                float4 bj = bb[j];                 // broadcast across warp
                float xx1 = fmaxf(bi.x, bj.x);
                float yy1 = fmaxf(bi.y, bj.y);
                float xx2 = fminf(bi.z, bj.z);
                float yy2 = fminf(bi.w, bj.w);
                float w_ = fmaxf(1e-28f, xx2 - xx1);
                float h_ = fmaxf(1e-28f, yy2 - yy1);
                float inter = w_ * h_;
                float aJ = (bj.z - bj.x) * (bj.w - bj.y);
                float denom = (aI + aJ) - inter;
                if (denom > 0.0f && inter > 0.599f * denom) {
                    if (inter / denom > 0.6f) bits |= (1u << (j & 31));
                }
            }
            mask[tid * NW + w] = bits;
            any |= bits;
        }
    }
    unsigned bal = __ballot_sync(0xFFFFFFFFu, any != 0);
    if ((tid & 31) == 0) flagw[tid >> 5] = bal;
    __syncthreads();

    // ---- serial OR-scan: one thread, register-resident, flag-gated row loads ----
    if (tid == 0) {
        unsigned rem[NW], fl[NW];
        #pragma unroll
        for (int w = 0; w < NW; w++) { rem[w] = 0; fl[w] = flagw[w]; }

        #pragma unroll
        for (int w = 0; w < NW; w++) {
            if (w * 32 < n) {
                int bend = min(32, n - w * 32);
                for (int b = 0; b < bend; b++) {
                    if (!((rem[w] >> b) & 1u)) {
                        int i = w * 32 + b;
                        out[(size_t)((int)(keys[i] & 0xFFFFFFFFULL)) * 7 + 6] = 1.0f;
                        if ((fl[w] >> b) & 1u) {
                            const uint4* row = (const uint4*)&mask[i * NW];
                            uint4 m0 = row[0], m1 = row[1], m2 = row[2], m3 = row[3];
                            rem[0]  |= m0.x; rem[1]  |= m0.y; rem[2]  |= m0.z; rem[3]  |= m0.w;
                            rem[4]  |= m1.x; rem[5]  |= m1.y; rem[6]  |= m1.z; rem[7]  |= m1.w;
                            rem[8]  |= m2.x; rem[9]  |= m2.y; rem[10] |= m2.z; rem[11] |= m2.w;
                            rem[12] |= m3.x; rem[13] |= m3.y; rem[14] |= m3.z; rem[15] |= m3.w;
                        }
                    }
                }
            }
        }
    }
}

extern "C" void kernel_launch(void* const* d_in, const int* in_sizes, int n_in,
                              void* d_out, int out_size) {
    const float* ps = (const float*)d_in[0];
    const float* pm = (const float*)d_in[1];
    const float* pl = (const float*)d_in[2];
    float* out = (float*)d_out;

    decode_kernel<<<(NTOT * TPA + 255) / 256, 256>>>(ps, pm, pl, out);
    nms_kernel<<<NCLS, 512>>>(out);
}

// round 7
// speedup vs baseline: 4.1310x; 1.0180x over previous
#include <cuda_runtime.h>
#include <cstdint>

#define NCLS 80
#define CAP  512          // per-class candidate cap (mean 315, max ~375 for seed 0)
#define NW   (CAP / 32)   // 16 mask words per row
#define NTOT 25200        // (6400+1600+400)*3
#define TPA  8            // threads per anchor in decode
#define CPA  (NCLS / TPA) // 10 classes per thread

// Scratch: per-class candidate lists (key = (~score_bits)<<32 | anchor_idx)
__device__ int d_count[NCLS];                       // zero-initialized at load
__device__ unsigned long long d_list[NCLS * CAP];
__device__ float4 d_boxes[NTOT];                    // decoded boxes for fast gather

__constant__ float c_anch[9][2] = {
    {10.f,13.f},{16.f,30.f},{33.f,23.f},
    {30.f,61.f},{62.f,45.f},{59.f,119.f},
    {116.f,90.f},{156.f,198.f},{373.f,326.f}
};

__device__ __forceinline__ float sigm(float x) { return 1.0f / (1.0f + expf(-x)); }

// 8 threads cooperate per anchor. Class logits cached in registers (one read),
// max/argmax + exp-sum reduced across the 8-lane segment via shfl.
__global__ void __launch_bounds__(256) decode_kernel(const float* __restrict__ ps,
                                                     const float* __restrict__ pm,
                                                     const float* __restrict__ pl,
                                                     float* __restrict__ out) {
    int t = blockIdx.x * blockDim.x + threadIdx.x;
    int aidx = t >> 3;
    int q    = t & (TPA - 1);
    if (aidx >= NTOT) return;

    const float* p; int HW, lvl, gbase, tl, ws;
    float stridev;
    if (aidx < 19200)      { p = ps; HW = 6400; stridev =  8.f; lvl = 0; gbase = 0;     tl = aidx;         ws = 80; }
    else if (aidx < 24000) { p = pm; HW = 1600; stridev = 16.f; lvl = 1; gbase = 19200; tl = aidx - 19200; ws = 40; }
    else                   { p = pl; HW =  400; stridev = 32.f; lvl = 2; gbase = 24000; tl = aidx - 24000; ws = 20; }

    int a = tl / HW;
    int i = tl - a * HW;

    const float* pc = p + (size_t)(3 + a * 80) * HW + i;
    float v[CPA];
    #pragma unroll
    for (int j = 0; j < CPA; j++)
        v[j] = pc[(size_t)(q * CPA + j) * HW];

    float m = v[0];
    int am = q * CPA;
    #pragma unroll
    for (int j = 1; j < CPA; j++)
        if (v[j] > m) { m = v[j]; am = q * CPA + j; }

    #pragma unroll
    for (int d = TPA / 2; d > 0; d >>= 1) {
        float om = __shfl_down_sync(0xFFFFFFFFu, m,  d, TPA);
        int   oa = __shfl_down_sync(0xFFFFFFFFu, am, d, TPA);
        if (om > m || (om == m && oa < am)) { m = om; am = oa; }
    }
    m  = __shfl_sync(0xFFFFFFFFu, m,  0, TPA);
    am = __shfl_sync(0xFFFFFFFFu, am, 0, TPA);

    float s = 0.0f;
    #pragma unroll
    for (int j = 0; j < CPA; j++)
        s += expf(v[j] - m);
    #pragma unroll
    for (int d = TPA / 2; d > 0; d >>= 1)
        s += __shfl_down_sync(0xFFFFFFFFu, s, d, TPA);

    if (q != 0) return;

    const float* pr = p + (size_t)(243 + a * 4) * HW + i;
    float gx = (float)(i % ws);
    float gy = (float)(i / ws);
    float cx = (sigm(pr[0])          + gx) * stridev;
    float cy = (sigm(pr[(size_t)HW]) + gy) * stridev;
    float bw = expf(pr[(size_t)2 * HW]) * c_anch[lvl * 3 + a][0];
    float bh = expf(pr[(size_t)3 * HW]) * c_anch[lvl * 3 + a][1];

    float x1 = fminf(fmaxf((cx - bw * 0.5f) / 640.0f, 0.0f), 1.0f);
    float y1 = fminf(fmaxf((cy - bh * 0.5f) / 640.0f, 0.0f), 1.0f);
    float x2 = fminf(fmaxf((cx + bw * 0.5f) / 640.0f, 0.0f), 1.0f);
    float y2 = fminf(fmaxf((cy + bh * 0.5f) / 640.0f, 0.0f), 1.0f);

    float obj   = sigm(p[(size_t)a * HW + i]);
    float score = (1.0f / s) * obj;

    int g = gbase + i * 3 + a;
    float* o = out + (size_t)g * 7;
    o[0] = x1; o[1] = y1; o[2] = x2; o[3] = y2;
    o[4] = score;
    o[5] = (float)am;
    o[6] = 0.0f;
    d_boxes[g] = make_float4(x1, y1, x2, y2);

    if (score >= 0.001f) {
        unsigned long long key =
            (((unsigned long long)(0xFFFFFFFFu - __float_as_uint(score))) << 32) |
            (unsigned long long)(unsigned)g;
        int pos = atomicAdd(&d_count[am], 1);
        if (pos < CAP) d_list[(size_t)am * CAP + pos] = key;
    }
}

// One block (512 threads) per class.
// 1) hybrid register/shfl bitonic sort (keys desc by score)
// 2) row-per-thread suppression-mask build into a TRANSPOSED matrix
//    maskT[w*CAP + i]: lanes (consecutive i) store consecutive words ->
//    conflict-free STS; bb[j] LDS is a warp broadcast.
// 3) single-thread OR-scan, flag-gated; row i read as 16 stride-CAP LDS.
__global__ void __launch_bounds__(512, 1) nms_kernel(float* __restrict__ out) {
    int c   = blockIdx.x;
    int tid = threadIdx.x;

    __shared__ unsigned long long keys[CAP];     //  4 KB
    __shared__ float4  bb[CAP];                  //  8 KB
    __shared__ unsigned maskT[NW * CAP];         // 32 KB transposed suppression matrix
    __shared__ unsigned flagw[NW];               // per-row any-suppression bits
    __shared__ int sn;

    if (tid == 0) {
        int nn = d_count[c];
        sn = (nn > CAP) ? CAP : nn;
        d_count[c] = 0;                          // reset for next replay
    }

    // coalesced, conflict-free zero of the mask matrix (hidden behind the sort)
    {
        uint4 z = make_uint4(0, 0, 0, 0);
        uint4* mz = (uint4*)maskT;
        #pragma unroll
        for (int k = 0; k < (NW * CAP / 4) / 512; k++)
            mz[tid + k * 512] = z;
    }
    __syncthreads();
    int n = sn;

    // ---- load keys into registers (sentinel pad) ----
    unsigned long long r = (tid < n) ? d_list[(size_t)c * CAP + tid]
                                     : 0xFFFFFFFFFFFFFFFFULL;

    // ---- bitonic sort (ascending key = descending score, idx asc) ----
    #pragma unroll
    for (int k = 2; k <= 32; k <<= 1) {
        bool up = ((tid & k) == 0);
        #pragma unroll
        for (int j = k >> 1; j >= 1; j >>= 1) {
            unsigned long long o = __shfl_xor_sync(0xFFFFFFFFu, r, j);
            bool takeMin = (((tid & j) == 0) == up);
            bool less = (o < r);
            r = takeMin ? (less ? o : r) : (less ? r : o);
        }
    }
    #pragma unroll
    for (int k = 64; k <= CAP; k <<= 1) {
        bool up = ((tid & k) == 0);
        for (int j = k >> 1; j >= 32; j >>= 1) {
            keys[tid] = r;
            __syncthreads();
            unsigned long long o = keys[tid ^ j];
            bool takeMin = (((tid & j) == 0) == up);
            bool less = (o < r);
            r = takeMin ? (less ? o : r) : (less ? r : o);
            __syncthreads();
        }
        #pragma unroll
        for (int j = 16; j >= 1; j >>= 1) {
            unsigned long long o = __shfl_xor_sync(0xFFFFFFFFu, r, j);
            bool takeMin = (((tid & j) == 0) == up);
            bool less = (o < r);
            r = takeMin ? (less ? o : r) : (less ? r : o);
        }
    }
    keys[tid] = r;
    __syncthreads();

    // ---- gather boxes in sorted order with the reference's class offset ----
    float off = 2.0f * (float)c;
    if (tid < n) {
        int idx = (int)(keys[tid] & 0xFFFFFFFFULL);
        float4 b = d_boxes[idx];                 // one LDG.128
        bb[tid] = make_float4(b.x + off, b.y + off, b.z + off, b.w + off);
    }
    __syncthreads();

    // ---- mask build: thread tid owns row i=tid; j uniform across warp ----
    unsigned any = 0;
    if (tid < n) {
        float4 bi = bb[tid];
        float aI = (bi.z - bi.x) * (bi.w - bi.y);
        int wbeg = (tid + 1) >> 5;
        int wend = (n + 31) >> 5;
        for (int w = wbeg; w < wend; w++) {
            int j0   = w << 5;
            int jbeg = max(j0, tid + 1);
            int jend = min(j0 + 32, n);
            unsigned bits = 0;
            for (int j = jbeg; j < jend; j++) {
                float4 bj = bb[j];                 // broadcast across warp
                float xx1 = fmaxf(bi.x, bj.x);
                float yy1 = fmaxf(bi.y, bj.y);
                float xx2 = fminf(bi.z, bj.z);
                float yy2 = fminf(bi.w, bj.w);
                float w_ = fmaxf(1e-28f, xx2 - xx1);
                float h_ = fmaxf(1e-28f, yy2 - yy1);
                float inter = w_ * h_;
                float aJ = (bj.z - bj.x) * (bj.w - bj.y);
                float denom = (aI + aJ) - inter;
                if (denom > 0.0f && inter > 0.599f * denom) {
                    if (inter / denom > 0.6f) bits |= (1u << (j & 31));
                }
            }
            if (bits) maskT[w * CAP + tid] = bits;   // conflict-free STS
            any |= bits;
        }
    }
    unsigned bal = __ballot_sync(0xFFFFFFFFu, any != 0);
    if ((tid & 31) == 0) flagw[tid >> 5] = bal;
    __syncthreads();

    // ---- serial OR-scan: one thread, register-resident, flag-gated ----
    if (tid == 0) {
        unsigned rem[NW], fl[NW];
        #pragma unroll
        for (int w = 0; w < NW; w++) { rem[w] = 0; fl[w] = flagw[w]; }

        #pragma unroll
        for (int w = 0; w < NW; w++) {
            if (w * 32 < n) {
                int bend = min(32, n - w * 32);
                for (int b = 0; b < bend; b++) {
                    if (!((rem[w] >> b) & 1u)) {
                        int i = w * 32 + b;
                        out[(size_t)((int)(keys[i] & 0xFFFFFFFFULL)) * 7 + 6] = 1.0f;
                        if ((fl[w] >> b) & 1u) {
                            #pragma unroll
                            for (int ww = 0; ww < NW; ww++)
                                rem[ww] |= maskT[ww * CAP + i];
                        }
                    }
                }
            }
        }
    }
}

extern "C" void kernel_launch(void* const* d_in, const int* in_sizes, int n_in,
                              void* d_out, int out_size) {
    const float* ps = (const float*)d_in[0];
    const float* pm = (const float*)d_in[1];
    const float* pl = (const float*)d_in[2];
    float* out = (float*)d_out;

    decode_kernel<<<(NTOT * TPA + 255) / 256, 256>>>(ps, pm, pl, out);
    nms_kernel<<<NCLS, 512>>>(out);
}